// round 4
// baseline (speedup 1.0000x reference)
#include <cuda_runtime.h>
#include <cuda_bf16.h>
#include <math.h>
#include <stdint.h>

// ---------------- problem constants ----------------
#define B_   2
#define NQ_  8192
#define DM_  256
#define NH_  6
#define DH_  64
#define NL_  3
#define NP_  9
#define NHD_ (NH_*DH_)            // 384
#define NOFF_ (NH_*NL_*NP_*2)     // 324
#define NATT_ (NH_*NL_*NP_)       // 162
#define TOTHW_ 10080              // 7680+1920+480

// level tables
__device__ __constant__ int   c_W[3]   = {160, 80, 40};
__device__ __constant__ int   c_H[3]   = {48, 24, 12};
__device__ __constant__ int   c_OFF[3] = {0, 7680, 9600};
__device__ __constant__ float c_SX[3]  = {160.f/1280.f, 80.f/1280.f, 40.f/1280.f};
__device__ __constant__ float c_SY[3]  = {48.f/384.f, 24.f/384.f, 12.f/384.f};

// ---------------- scratch (no allocs allowed) ----------------
__device__ float g_v   [(size_t)B_ * TOTHW_ * NHD_];   // value projection, [b][pix][h*64+d]
__device__ float g_off [(size_t)B_ * NQ_ * NOFF_];
__device__ float g_attn[(size_t)B_ * NQ_ * NATT_];
__device__ float g_mid [(size_t)B_ * NQ_ * NHD_];

// ================= tensor-core GEMM (bf16 3-term split, fp32 accurate) =================
// C[M,N] = op(A)[M,K] @ W[K,N] + bias
// transLD==0 : A row-major [M,K] (+ optional A2 added elementwise)
// transLD>0  : A[m,k] = A[k*transLD + m]   (feature maps [K, M])
// Block tile 128x64, BK=32, 8 warps (4m x 2n), warp tile 32x32, mma.m16n8k16.bf16.

__device__ __forceinline__ void split2(float f0, float f1, uint32_t& hi, uint32_t& lo) {
    __nv_bfloat16 h0 = __float2bfloat16_rn(f0);
    __nv_bfloat16 h1 = __float2bfloat16_rn(f1);
    float r0 = f0 - __bfloat162float(h0);
    float r1 = f1 - __bfloat162float(h1);
    __nv_bfloat16 l0 = __float2bfloat16_rn(r0);
    __nv_bfloat16 l1 = __float2bfloat16_rn(r1);
    __nv_bfloat162 H; H.x = h0; H.y = h1;
    __nv_bfloat162 L; L.x = l0; L.y = l1;
    hi = *reinterpret_cast<uint32_t*>(&H);
    lo = *reinterpret_cast<uint32_t*>(&L);
}

#define MMA16816(d, a, b) \
  asm volatile("mma.sync.aligned.m16n8k16.row.col.f32.bf16.bf16.f32 " \
    "{%0,%1,%2,%3},{%4,%5,%6,%7},{%8,%9},{%0,%1,%2,%3};" \
    : "+f"((d)[0]), "+f"((d)[1]), "+f"((d)[2]), "+f"((d)[3]) \
    : "r"((a)[0]), "r"((a)[1]), "r"((a)[2]), "r"((a)[3]), "r"((b)[0]), "r"((b)[1]))

#define AS_ 136
#define BS_ 72
#define A_WORDS (16*AS_)            // 2176
#define B_WORDS (16*BS_)            // 1152
#define STAGE_W (2*A_WORDS + 2*B_WORDS)   // 6656 words
#define SMEM_BYTES (2*STAGE_W*4)          // 53248

__global__ __launch_bounds__(256, 2)
void mma_gemm(const float* __restrict__ A, const float* __restrict__ A2,
              const float* __restrict__ W, const float* __restrict__ bias,
              float* __restrict__ C, int M, int N, int K, int transLD,
              long strideA, long strideC)
{
    extern __shared__ uint32_t sm[];

    const int bz = blockIdx.z;
    const float* Ab  = A + (long)bz * strideA;
    const float* A2b = A2 ? (A2 + (long)bz * strideA) : nullptr;
    float* Cb = C + (long)bz * strideC;

    const int m0 = blockIdx.y * 128;
    const int n0 = blockIdx.x * 64;
    const int tid  = threadIdx.x;
    const int lane = tid & 31;
    const int warp = tid >> 5;
    const int wm = warp & 3, wn = warp >> 2;
    const int r = lane >> 2, cc = lane & 3;

    float acc[2][4][4];
    #pragma unroll
    for (int i = 0; i < 2; i++)
        #pragma unroll
        for (int j = 0; j < 4; j++)
            #pragma unroll
            for (int t = 0; t < 4; t++) acc[i][j][t] = 0.f;

    const int nst = K >> 5;
    float4 pa[4];
    float  pb[8];

    // ---- global load of k-tile kt into registers ----
    #define GLOAD(kt) { \
      const int k0g = (kt) << 5; \
      if (transLD == 0) { \
        _Pragma("unroll") for (int p = 0; p < 4; p++) { \
          int m = (tid >> 3) + p * 32; \
          int kq = (tid & 7) * 4; \
          float4 v = make_float4(0.f,0.f,0.f,0.f); \
          if (m0 + m < M) { \
            v = *(const float4*)&Ab[(long)(m0 + m) * K + k0g + kq]; \
            if (A2b) { \
              float4 u = *(const float4*)&A2b[(long)(m0 + m) * K + k0g + kq]; \
              v.x += u.x; v.y += u.y; v.z += u.z; v.w += u.w; \
            } \
          } \
          pa[p] = v; \
        } \
      } else { \
        _Pragma("unroll") for (int p = 0; p < 2; p++) { \
          int kp = (tid >> 5) + p * 8; \
          int ml = (tid & 31) * 4; \
          float4 v0 = make_float4(0.f,0.f,0.f,0.f), v1 = v0; \
          if (m0 + ml < M) { \
            v0 = *(const float4*)&Ab[(long)(k0g + 2*kp    ) * transLD + m0 + ml]; \
            v1 = *(const float4*)&Ab[(long)(k0g + 2*kp + 1) * transLD + m0 + ml]; \
          } \
          pa[p*2] = v0; pa[p*2+1] = v1; \
        } \
      } \
      { int kp = tid >> 4; int nq = (tid & 15) * 4; \
        _Pragma("unroll") for (int i = 0; i < 4; i++) { \
          int n = n0 + nq + i; \
          pb[i]   = (n < N) ? W[(long)(k0g + 2*kp    ) * N + n] : 0.f; \
          pb[4+i] = (n < N) ? W[(long)(k0g + 2*kp + 1) * N + n] : 0.f; \
        } } \
    }

    // ---- convert + store registers into smem stage buf ----
    #define GSTORE(buf) { \
      uint32_t* Ah = sm + (buf) * STAGE_W; \
      uint32_t* Al = Ah + A_WORDS; \
      uint32_t* Bh = Al + A_WORDS; \
      uint32_t* Bl = Bh + B_WORDS; \
      if (transLD == 0) { \
        _Pragma("unroll") for (int p = 0; p < 4; p++) { \
          int m = (tid >> 3) + p * 32; \
          int kp0 = (tid & 7) * 2; \
          uint32_t h0,l0,h1,l1; \
          split2(pa[p].x, pa[p].y, h0, l0); \
          split2(pa[p].z, pa[p].w, h1, l1); \
          Ah[kp0*AS_ + m] = h0; Ah[(kp0+1)*AS_ + m] = h1; \
          Al[kp0*AS_ + m] = l0; Al[(kp0+1)*AS_ + m] = l1; \
        } \
      } else { \
        _Pragma("unroll") for (int p = 0; p < 2; p++) { \
          int kp = (tid >> 5) + p * 8; \
          int ml = (tid & 31) * 4; \
          const float* f0 = (const float*)&pa[p*2]; \
          const float* f1 = (const float*)&pa[p*2+1]; \
          uint32_t h[4], l[4]; \
          _Pragma("unroll") for (int i = 0; i < 4; i++) split2(f0[i], f1[i], h[i], l[i]); \
          *(uint4*)&Ah[kp*AS_ + ml] = make_uint4(h[0],h[1],h[2],h[3]); \
          *(uint4*)&Al[kp*AS_ + ml] = make_uint4(l[0],l[1],l[2],l[3]); \
        } \
      } \
      { int kp = tid >> 4; int nq = (tid & 15) * 4; \
        uint32_t h[4], l[4]; \
        _Pragma("unroll") for (int i = 0; i < 4; i++) split2(pb[i], pb[4+i], h[i], l[i]); \
        *(uint4*)&Bh[kp*BS_ + nq] = make_uint4(h[0],h[1],h[2],h[3]); \
        *(uint4*)&Bl[kp*BS_ + nq] = make_uint4(l[0],l[1],l[2],l[3]); \
      } \
    }

    // ---- compute a stage ----
    #define COMPUTE(buf) { \
      const uint32_t* Ah = sm + (buf) * STAGE_W; \
      const uint32_t* Al = Ah + A_WORDS; \
      const uint32_t* Bh = Al + A_WORDS; \
      const uint32_t* Bl = Bh + B_WORDS; \
      _Pragma("unroll") for (int kk = 0; kk < 2; kk++) { \
        const int kb = kk * 8 + cc; \
        uint32_t ah[2][4], al[2][4], bh[4][2], bl[4][2]; \
        _Pragma("unroll") for (int mt = 0; mt < 2; mt++) { \
          int mrow = wm * 32 + mt * 16 + r; \
          ah[mt][0] = Ah[kb*AS_ + mrow];     ah[mt][1] = Ah[kb*AS_ + mrow + 8]; \
          ah[mt][2] = Ah[(kb+4)*AS_ + mrow]; ah[mt][3] = Ah[(kb+4)*AS_ + mrow + 8]; \
          al[mt][0] = Al[kb*AS_ + mrow];     al[mt][1] = Al[kb*AS_ + mrow + 8]; \
          al[mt][2] = Al[(kb+4)*AS_ + mrow]; al[mt][3] = Al[(kb+4)*AS_ + mrow + 8]; \
        } \
        _Pragma("unroll") for (int nt = 0; nt < 4; nt++) { \
          int ncol = wn * 32 + nt * 8 + r; \
          bh[nt][0] = Bh[kb*BS_ + ncol]; bh[nt][1] = Bh[(kb+4)*BS_ + ncol]; \
          bl[nt][0] = Bl[kb*BS_ + ncol]; bl[nt][1] = Bl[(kb+4)*BS_ + ncol]; \
        } \
        _Pragma("unroll") for (int mt = 0; mt < 2; mt++) \
          _Pragma("unroll") for (int nt = 0; nt < 4; nt++) { \
            MMA16816(acc[mt][nt], ah[mt], bh[nt]); \
            MMA16816(acc[mt][nt], al[mt], bh[nt]); \
            MMA16816(acc[mt][nt], ah[mt], bl[nt]); \
          } \
      } \
    }

    GLOAD(0);
    GSTORE(0);
    __syncthreads();

    for (int s = 0; s < nst; s++) {
        if (s + 1 < nst) GLOAD(s + 1);
        COMPUTE(s & 1);
        if (s + 1 < nst) GSTORE((s + 1) & 1);
        __syncthreads();
    }

    // ---- epilogue ----
    #pragma unroll
    for (int mt = 0; mt < 2; mt++) {
        int m = m0 + wm * 32 + mt * 16 + r;
        #pragma unroll
        for (int nt = 0; nt < 4; nt++) {
            int n = n0 + wn * 32 + nt * 8 + cc * 2;
            const float* d = acc[mt][nt];
            if (m < M) {
                if (n < N)     Cb[(long)m * N + n]     = d[0] + bias[n];
                if (n + 1 < N) Cb[(long)m * N + n + 1] = d[1] + bias[n + 1];
            }
            if (m + 8 < M) {
                if (n < N)     Cb[(long)(m + 8) * N + n]     = d[2] + bias[n];
                if (n + 1 < N) Cb[(long)(m + 8) * N + n + 1] = d[3] + bias[n + 1];
            }
        }
    }
}

// ---------------- sampler: projection + softmax + bilinear gather + attn-weighted sum ----------------
__global__ __launch_bounds__(384)
void sample_kernel(const float* __restrict__ coor,
                   const float* __restrict__ cam2img,
                   const float* __restrict__ lidar2cam)
{
    const int q = blockIdx.x;
    const int b = blockIdx.y;
    const int tid = threadIdx.x;
    const int h = tid >> 6;
    const int d = tid & 63;

    __shared__ float s_uv[2];
    __shared__ float s_logit[NH_][NL_*NP_];
    __shared__ float s_w[NH_][NL_*NP_];
    __shared__ int   s_idx[NH_][NL_*NP_][4];
    __shared__ float s_bw[NH_][NL_*NP_][4];

    if (tid == 0) {
        const float* L  = lidar2cam + b * 16;
        const float* Kc = cam2img + b * 16;
        float p0 = coor[((long)b * NQ_ + q) * 3 + 0];
        float p1 = coor[((long)b * NQ_ + q) * 3 + 1];
        float p2 = coor[((long)b * NQ_ + q) * 3 + 2];
        float pc[3], pr[3];
        #pragma unroll
        for (int i = 0; i < 3; i++)
            pc[i] = L[i*4+0]*p0 + L[i*4+1]*p1 + L[i*4+2]*p2 + L[i*4+3];
        #pragma unroll
        for (int i = 0; i < 3; i++)
            pr[i] = Kc[i*4+0]*pc[0] + Kc[i*4+1]*pc[1] + Kc[i*4+2]*pc[2] + Kc[i*4+3];
        s_uv[0] = pr[0] / pr[2];
        s_uv[1] = pr[1] / pr[2];
    }
    __syncthreads();

    const long bq = (long)b * NQ_ + q;

    if (d < NL_*NP_) {
        const int j = d;
        const int l = j / NP_;
        const int p = j - l * NP_;

        s_logit[h][j] = g_attn[bq * NATT_ + h * (NL_*NP_) + j];

        const float* offp = &g_off[bq * NOFF_ + h * (NL_*NP_*2) + l * (NP_*2) + p * 2];
        float px = s_uv[0] * c_SX[l] + offp[0] - 0.5f;
        float py = s_uv[1] * c_SY[l] + offp[1] - 0.5f;
        float x0 = floorf(px), y0 = floorf(py);
        float fx = px - x0, fy = py - y0;
        const int wl = c_W[l], hl = c_H[l];
        const int base_l = b * TOTHW_ + c_OFF[l];

        #pragma unroll
        for (int c = 0; c < 4; c++) {
            int dx = c & 1, dy = c >> 1;
            float xi = x0 + dx, yi = y0 + dy;
            bool valid = (xi >= 0.f) && (xi < (float)wl) && (yi >= 0.f) && (yi < (float)hl);
            float wgt = (dx ? fx : 1.f - fx) * (dy ? fy : 1.f - fy);
            float xc = fminf(fmaxf(xi, 0.f), (float)(wl - 1));
            float yc = fminf(fmaxf(yi, 0.f), (float)(hl - 1));
            int pix = (int)yc * wl + (int)xc;
            s_idx[h][j][c] = (base_l + pix) * NHD_ + h * DH_;
            s_bw[h][j][c]  = valid ? wgt : 0.f;
        }
    }
    __syncthreads();

    if (d < NL_*NP_) {
        float mx = -1e30f;
        #pragma unroll
        for (int jj = 0; jj < NL_*NP_; jj++) mx = fmaxf(mx, s_logit[h][jj]);
        s_w[h][d] = expf(s_logit[h][d] - mx);
    }
    __syncthreads();

    float sum = 0.f;
    #pragma unroll
    for (int jj = 0; jj < NL_*NP_; jj++) sum += s_w[h][jj];
    const float rsum = 1.f / sum;

    float acc = 0.f;
    #pragma unroll 3
    for (int j = 0; j < NL_*NP_; j++) {
        float aw = s_w[h][j] * rsum;
        const int*   id = s_idx[h][j];
        const float* bw = s_bw[h][j];
        float s = bw[0] * g_v[id[0] + d]
                + bw[1] * g_v[id[1] + d]
                + bw[2] * g_v[id[2] + d]
                + bw[3] * g_v[id[3] + d];
        acc += aw * s;
    }
    g_mid[bq * NHD_ + h * DH_ + d] = acc;
}

// ---------------- host launcher ----------------
extern "C" void kernel_launch(void* const* d_in, const int* in_sizes, int n_in,
                              void* d_out, int out_size)
{
    const float* x         = (const float*)d_in[0];
    const float* pe        = (const float*)d_in[1];
    const float* coor      = (const float*)d_in[2];
    const float* cam2img   = (const float*)d_in[3];
    const float* lidar2cam = (const float*)d_in[4];
    const float* feat0     = (const float*)d_in[5];
    const float* feat1     = (const float*)d_in[6];
    const float* feat2     = (const float*)d_in[7];
    const float* W_value   = (const float*)d_in[8];
    const float* b_value   = (const float*)d_in[9];
    const float* W_off     = (const float*)d_in[10];
    const float* b_off     = (const float*)d_in[11];
    const float* W_attn    = (const float*)d_in[12];
    const float* b_attn    = (const float*)d_in[13];
    const float* W_out     = (const float*)d_in[14];
    const float* b_out     = (const float*)d_in[15];
    float* out = (float*)d_out;

    float *pv, *poff, *pattn, *pmid;
    cudaGetSymbolAddress((void**)&pv, g_v);
    cudaGetSymbolAddress((void**)&poff, g_off);
    cudaGetSymbolAddress((void**)&pattn, g_attn);
    cudaGetSymbolAddress((void**)&pmid, g_mid);

    cudaFuncSetAttribute(mma_gemm, cudaFuncAttributeMaxDynamicSharedMemorySize, SMEM_BYTES);

    const int hw[3]  = {7680, 1920, 480};
    const int off[3] = {0, 7680, 9600};
    const float* feats[3] = {feat0, feat1, feat2};

    // 1) value projection per level (A transposed: feat is [B, 256, hw])
    for (int l = 0; l < 3; l++) {
        dim3 grid((NHD_ + 63) / 64, (hw[l] + 127) / 128, B_);
        mma_gemm<<<grid, 256, SMEM_BYTES>>>(feats[l], nullptr, W_value, b_value,
                                            pv + (long)off[l] * NHD_,
                                            hw[l], NHD_, DM_, /*transLD=*/hw[l],
                                            (long)DM_ * hw[l], (long)TOTHW_ * NHD_);
    }

    // 2) offsets GEMM: (x+pe) @ W_off
    {
        dim3 grid((NOFF_ + 63) / 64, (B_ * NQ_ + 127) / 128, 1);
        mma_gemm<<<grid, 256, SMEM_BYTES>>>(x, pe, W_off, b_off, poff,
                                            B_ * NQ_, NOFF_, DM_, 0, 0, 0);
    }

    // 3) attention logits GEMM: (x+pe) @ W_attn
    {
        dim3 grid((NATT_ + 63) / 64, (B_ * NQ_ + 127) / 128, 1);
        mma_gemm<<<grid, 256, SMEM_BYTES>>>(x, pe, W_attn, b_attn, pattn,
                                            B_ * NQ_, NATT_, DM_, 0, 0, 0);
    }

    // 4) projection + softmax + bilinear sampling + weighted accumulation
    {
        dim3 grid(NQ_, B_);
        sample_kernel<<<grid, 384>>>(coor, cam2img, lidar2cam);
    }

    // 5) output GEMM: mid @ W_out + b_out
    {
        dim3 grid((DM_ + 63) / 64, (B_ * NQ_ + 127) / 128, 1);
        mma_gemm<<<grid, 256, SMEM_BYTES>>>(pmid, nullptr, W_out, b_out, out,
                                            B_ * NQ_, DM_, NHD_, 0, 0, 0);
    }
}

// round 5
// speedup vs baseline: 1.1337x; 1.1337x over previous
#include <cuda_runtime.h>
#include <cuda_bf16.h>
#include <math.h>
#include <stdint.h>

// ---------------- problem constants ----------------
#define B_   2
#define NQ_  8192
#define DM_  256
#define NH_  6
#define DH_  64
#define NL_  3
#define NP_  9
#define NHD_ (NH_*DH_)            // 384
#define NOFF_ (NH_*NL_*NP_*2)     // 324
#define NATT_ (NH_*NL_*NP_)       // 162
#define TOTHW_ 10080              // 7680+1920+480

// level tables
__device__ __constant__ int   c_W[3]   = {160, 80, 40};
__device__ __constant__ int   c_H[3]   = {48, 24, 12};
__device__ __constant__ int   c_OFF[3] = {0, 7680, 9600};
__device__ __constant__ float c_SX[3]  = {160.f/1280.f, 80.f/1280.f, 40.f/1280.f};
__device__ __constant__ float c_SY[3]  = {48.f/384.f, 24.f/384.f, 12.f/384.f};

// ---------------- scratch (no allocs allowed) ----------------
__device__ float g_v   [(size_t)B_ * TOTHW_ * NHD_];
__device__ float g_off [(size_t)B_ * NQ_ * NOFF_];
__device__ float g_attn[(size_t)B_ * NQ_ * NATT_];

// bf16 hi/lo planes
__device__ __nv_bfloat16 g_qh [(size_t)B_ * NQ_ * DM_];
__device__ __nv_bfloat16 g_ql [(size_t)B_ * NQ_ * DM_];
__device__ __nv_bfloat16 g_fh [(size_t)B_ * TOTHW_ * DM_];
__device__ __nv_bfloat16 g_fl [(size_t)B_ * TOTHW_ * DM_];
__device__ __nv_bfloat16 g_midh[(size_t)B_ * NQ_ * NHD_];
__device__ __nv_bfloat16 g_midl[(size_t)B_ * NQ_ * NHD_];

// transposed weights [N][K], packed: Wv(384x256) | Woff(324x256) | Wattn(162x256) | Wout(256x384)
#define WV_OFF  0
#define WOFF_OFF (384*256)
#define WATT_OFF (WOFF_OFF + 324*256)
#define WOUT_OFF (WATT_OFF + 162*256)
#define WTOT_ (WOUT_OFF + 256*384)
__device__ __nv_bfloat16 g_wh[WTOT_];
__device__ __nv_bfloat16 g_wl[WTOT_];

// ================= prep kernels =================
__global__ __launch_bounds__(256)
void add_split_kernel(const float* __restrict__ x, const float* __restrict__ pe,
                      __nv_bfloat16* __restrict__ oh, __nv_bfloat16* __restrict__ ol, int n4)
{
    int i = blockIdx.x * blockDim.x + threadIdx.x;
    if (i >= n4) return;
    float4 a = reinterpret_cast<const float4*>(x)[i];
    float4 b = reinterpret_cast<const float4*>(pe)[i];
    float v[4] = {a.x + b.x, a.y + b.y, a.z + b.z, a.w + b.w};
    __nv_bfloat16 h[4], l[4];
    #pragma unroll
    for (int j = 0; j < 4; j++) {
        h[j] = __float2bfloat16_rn(v[j]);
        l[j] = __float2bfloat16_rn(v[j] - __bfloat162float(h[j]));
    }
    *reinterpret_cast<uint2*>(oh + (size_t)i*4) = *reinterpret_cast<uint2*>(h);
    *reinterpret_cast<uint2*>(ol + (size_t)i*4) = *reinterpret_cast<uint2*>(l);
}

// transpose + split: in [R][C] fp32 -> out planes [C][R] bf16 (batched via strides)
__global__ __launch_bounds__(256)
void transpose_split_kernel(const float* __restrict__ in,
                            __nv_bfloat16* __restrict__ oh, __nv_bfloat16* __restrict__ ol,
                            int R, int C, long inStride, long outStride)
{
    __shared__ float t[32][33];
    const int b = blockIdx.z;
    const float* ip = in + (long)b * inStride;
    const int c0 = blockIdx.x * 32, r0 = blockIdx.y * 32;
    const int tx = threadIdx.x & 31, ty = threadIdx.x >> 5; // 32x8

    #pragma unroll
    for (int i = 0; i < 32; i += 8) {
        int r = r0 + ty + i, c = c0 + tx;
        t[ty + i][tx] = (r < R && c < C) ? ip[(long)r * C + c] : 0.f;
    }
    __syncthreads();
    #pragma unroll
    for (int i = 0; i < 32; i += 8) {
        int c = c0 + ty + i, r = r0 + tx;
        if (c < C && r < R) {
            float v = t[tx][ty + i];
            __nv_bfloat16 h = __float2bfloat16_rn(v);
            long o = (long)b * outStride + (long)c * R + r;
            oh[o] = h;
            ol[o] = __float2bfloat16_rn(v - __bfloat162float(h));
        }
    }
}

// ================= bf16 tensor-core GEMM =================
// C[M,N] = (Ah+Al)[M,K] @ (Bh+Bl)[N,K]^T + bias   (3-term split)
#define BM 128
#define BN 64
#define BK 32
#define A_TILE_B (BM*BK*2)                 // 8192 B per plane
#define B_TILE_B (BN*BK*2)                 // 4096 B per plane
#define STAGE_B  (2*A_TILE_B + 2*B_TILE_B) // 24576 B
#define GEMM_SMEM (2*STAGE_B)              // 49152 B

#define MMA16816(d, a, b0v, b1v) \
  asm volatile("mma.sync.aligned.m16n8k16.row.col.f32.bf16.bf16.f32 " \
    "{%0,%1,%2,%3},{%4,%5,%6,%7},{%8,%9},{%0,%1,%2,%3};" \
    : "+f"((d)[0]), "+f"((d)[1]), "+f"((d)[2]), "+f"((d)[3]) \
    : "r"((a)[0]), "r"((a)[1]), "r"((a)[2]), "r"((a)[3]), "r"(b0v), "r"(b1v))

__device__ __forceinline__ uint32_t swz(uint32_t off) {
    return off ^ ((off >> 3) & 0x30);
}
__device__ __forceinline__ void ldsm4(uint32_t (&r)[4], uint32_t addr) {
    asm volatile("ldmatrix.sync.aligned.m8n8.x4.shared.b16 {%0,%1,%2,%3}, [%4];"
        : "=r"(r[0]), "=r"(r[1]), "=r"(r[2]), "=r"(r[3]) : "r"(addr));
}
__device__ __forceinline__ void cp16(uint32_t dst, const void* src, bool pred) {
    int sz = pred ? 16 : 0;
    asm volatile("cp.async.cg.shared.global [%0], [%1], 16, %2;\n"
                 :: "r"(dst), "l"(src), "r"(sz));
}

__global__ __launch_bounds__(256, 2)
void bf16_gemm(const __nv_bfloat16* __restrict__ Ah, const __nv_bfloat16* __restrict__ Al,
               const __nv_bfloat16* __restrict__ Bh, const __nv_bfloat16* __restrict__ Bl,
               const float* __restrict__ bias, float* __restrict__ C,
               int M, int N, int K)
{
    extern __shared__ uint8_t sm8[];
    uint32_t smb;
    asm("{ .reg .u64 t; cvta.to.shared.u64 t, %1; cvt.u32.u64 %0, t; }" : "=r"(smb) : "l"(sm8));

    const int m0 = blockIdx.y * BM;
    const int n0 = blockIdx.x * BN;
    const int tid = threadIdx.x;
    const int lane = tid & 31, warp = tid >> 5;
    const int wm = warp & 3, wn = warp >> 2;
    const int r = lane >> 2, cc = lane & 3;

    float acc[2][4][4];
    #pragma unroll
    for (int i = 0; i < 2; i++)
        #pragma unroll
        for (int j = 0; j < 4; j++)
            #pragma unroll
            for (int t = 0; t < 4; t++) acc[i][j][t] = 0.f;

    const int nst = K / BK;

    auto LOAD = [&](int s, int buf) {
        uint32_t base = smb + buf * STAGE_B;
        const int k0 = s * BK;
        #pragma unroll
        for (int half = 0; half < 2; half++) {
            int c = tid + half * 256;
            int row = c >> 2, col = c & 3;
            bool p = (m0 + row) < M;
            long g = (long)(p ? (m0 + row) : 0) * K + k0 + col * 8;
            uint32_t so = swz((uint32_t)(row * 64 + col * 16));
            cp16(base + so, Ah + g, p);
            cp16(base + A_TILE_B + so, Al + g, p);
        }
        {
            int row = tid >> 2, col = tid & 3;
            bool p = (n0 + row) < N;
            long g = (long)(p ? (n0 + row) : 0) * K + k0 + col * 8;
            uint32_t so = swz((uint32_t)(row * 64 + col * 16));
            cp16(base + 2 * A_TILE_B + so, Bh + g, p);
            cp16(base + 2 * A_TILE_B + B_TILE_B + so, Bl + g, p);
        }
        asm volatile("cp.async.commit_group;\n" ::: "memory");
    };

    auto COMPUTE = [&](int buf) {
        uint32_t base = smb + buf * STAGE_B;
        #pragma unroll
        for (int kk = 0; kk < 2; kk++) {
            uint32_t ah[2][4], al[2][4], bh[2][4], bl[2][4];
            #pragma unroll
            for (int mt = 0; mt < 2; mt++) {
                int row = wm * 32 + mt * 16 + (lane & 15);
                uint32_t off = swz((uint32_t)(row * 64 + (kk * 2 + (lane >> 4)) * 16));
                ldsm4(ah[mt], base + off);
                ldsm4(al[mt], base + A_TILE_B + off);
            }
            #pragma unroll
            for (int nt2 = 0; nt2 < 2; nt2++) {
                int row = wn * 32 + nt2 * 16 + (lane & 15);
                uint32_t off = swz((uint32_t)(row * 64 + (kk * 2 + (lane >> 4)) * 16));
                ldsm4(bh[nt2], base + 2 * A_TILE_B + off);
                ldsm4(bl[nt2], base + 2 * A_TILE_B + B_TILE_B + off);
            }
            #pragma unroll
            for (int mt = 0; mt < 2; mt++)
                #pragma unroll
                for (int nt = 0; nt < 4; nt++) {
                    int n2 = nt >> 1, hv = nt & 1;
                    MMA16816(acc[mt][nt], ah[mt], bh[n2][hv], bh[n2][hv + 2]);
                    MMA16816(acc[mt][nt], al[mt], bh[n2][hv], bh[n2][hv + 2]);
                    MMA16816(acc[mt][nt], ah[mt], bl[n2][hv], bl[n2][hv + 2]);
                }
        }
    };

    LOAD(0, 0);
    for (int s = 0; s < nst; s++) {
        asm volatile("cp.async.wait_group 0;\n" ::: "memory");
        __syncthreads();
        if (s + 1 < nst) LOAD(s + 1, (s + 1) & 1);
        COMPUTE(s & 1);
    }

    // epilogue
    #pragma unroll
    for (int mt = 0; mt < 2; mt++) {
        int m = m0 + wm * 32 + mt * 16 + r;
        #pragma unroll
        for (int nt = 0; nt < 4; nt++) {
            int n = n0 + wn * 32 + nt * 8 + cc * 2;
            const float* d = acc[mt][nt];
            if (m < M) {
                if (n < N)     C[(long)m * N + n]     = d[0] + bias[n];
                if (n + 1 < N) C[(long)m * N + n + 1] = d[1] + bias[n + 1];
            }
            if (m + 8 < M) {
                if (n < N)     C[(long)(m + 8) * N + n]     = d[2] + bias[n];
                if (n + 1 < N) C[(long)(m + 8) * N + n + 1] = d[3] + bias[n + 1];
            }
        }
    }
}

// ---------------- sampler ----------------
__global__ __launch_bounds__(384)
void sample_kernel(const float* __restrict__ coor,
                   const float* __restrict__ cam2img,
                   const float* __restrict__ lidar2cam)
{
    const int q = blockIdx.x;
    const int b = blockIdx.y;
    const int tid = threadIdx.x;
    const int h = tid >> 6;
    const int d = tid & 63;

    __shared__ float s_uv[2];
    __shared__ float s_logit[NH_][NL_*NP_];
    __shared__ float s_w[NH_][NL_*NP_];
    __shared__ int   s_idx[NH_][NL_*NP_][4];
    __shared__ float s_bw[NH_][NL_*NP_][4];

    if (tid == 0) {
        const float* L  = lidar2cam + b * 16;
        const float* Kc = cam2img + b * 16;
        float p0 = coor[((long)b * NQ_ + q) * 3 + 0];
        float p1 = coor[((long)b * NQ_ + q) * 3 + 1];
        float p2 = coor[((long)b * NQ_ + q) * 3 + 2];
        float pc[3], pr[3];
        #pragma unroll
        for (int i = 0; i < 3; i++)
            pc[i] = L[i*4+0]*p0 + L[i*4+1]*p1 + L[i*4+2]*p2 + L[i*4+3];
        #pragma unroll
        for (int i = 0; i < 3; i++)
            pr[i] = Kc[i*4+0]*pc[0] + Kc[i*4+1]*pc[1] + Kc[i*4+2]*pc[2] + Kc[i*4+3];
        s_uv[0] = pr[0] / pr[2];
        s_uv[1] = pr[1] / pr[2];
    }
    __syncthreads();

    const long bq = (long)b * NQ_ + q;

    if (d < NL_*NP_) {
        const int j = d;
        const int l = j / NP_;
        const int p = j - l * NP_;

        s_logit[h][j] = g_attn[bq * NATT_ + h * (NL_*NP_) + j];

        const float* offp = &g_off[bq * NOFF_ + h * (NL_*NP_*2) + l * (NP_*2) + p * 2];
        float px = s_uv[0] * c_SX[l] + offp[0] - 0.5f;
        float py = s_uv[1] * c_SY[l] + offp[1] - 0.5f;
        float x0 = floorf(px), y0 = floorf(py);
        float fx = px - x0, fy = py - y0;
        const int wl = c_W[l], hl = c_H[l];
        const int base_l = b * TOTHW_ + c_OFF[l];

        #pragma unroll
        for (int c = 0; c < 4; c++) {
            int dx = c & 1, dy = c >> 1;
            float xi = x0 + dx, yi = y0 + dy;
            bool valid = (xi >= 0.f) && (xi < (float)wl) && (yi >= 0.f) && (yi < (float)hl);
            float wgt = (dx ? fx : 1.f - fx) * (dy ? fy : 1.f - fy);
            float xc = fminf(fmaxf(xi, 0.f), (float)(wl - 1));
            float yc = fminf(fmaxf(yi, 0.f), (float)(hl - 1));
            int pix = (int)yc * wl + (int)xc;
            s_idx[h][j][c] = (base_l + pix) * NHD_ + h * DH_;
            s_bw[h][j][c]  = valid ? wgt : 0.f;
        }
    }
    __syncthreads();

    if (d < NL_*NP_) {
        float mx = -1e30f;
        #pragma unroll
        for (int jj = 0; jj < NL_*NP_; jj++) mx = fmaxf(mx, s_logit[h][jj]);
        s_w[h][d] = expf(s_logit[h][d] - mx);
    }
    __syncthreads();

    float sum = 0.f;
    #pragma unroll
    for (int jj = 0; jj < NL_*NP_; jj++) sum += s_w[h][jj];
    const float rsum = 1.f / sum;

    float acc = 0.f;
    #pragma unroll 3
    for (int j = 0; j < NL_*NP_; j++) {
        float aw = s_w[h][j] * rsum;
        const int*   id = s_idx[h][j];
        const float* bw = s_bw[h][j];
        float s = bw[0] * g_v[id[0] + d]
                + bw[1] * g_v[id[1] + d]
                + bw[2] * g_v[id[2] + d]
                + bw[3] * g_v[id[3] + d];
        acc += aw * s;
    }
    long oidx = bq * NHD_ + h * DH_ + d;
    __nv_bfloat16 hh = __float2bfloat16_rn(acc);
    g_midh[oidx] = hh;
    g_midl[oidx] = __float2bfloat16_rn(acc - __bfloat162float(hh));
}

// ---------------- host launcher ----------------
extern "C" void kernel_launch(void* const* d_in, const int* in_sizes, int n_in,
                              void* d_out, int out_size)
{
    const float* x         = (const float*)d_in[0];
    const float* pe        = (const float*)d_in[1];
    const float* coor      = (const float*)d_in[2];
    const float* cam2img   = (const float*)d_in[3];
    const float* lidar2cam = (const float*)d_in[4];
    const float* feat0     = (const float*)d_in[5];
    const float* feat1     = (const float*)d_in[6];
    const float* feat2     = (const float*)d_in[7];
    const float* W_value   = (const float*)d_in[8];
    const float* b_value   = (const float*)d_in[9];
    const float* W_off     = (const float*)d_in[10];
    const float* b_off     = (const float*)d_in[11];
    const float* W_attn    = (const float*)d_in[12];
    const float* b_attn    = (const float*)d_in[13];
    const float* W_out     = (const float*)d_in[14];
    const float* b_out     = (const float*)d_in[15];
    float* out = (float*)d_out;

    float *pv, *poff, *pattn;
    __nv_bfloat16 *pqh, *pql, *pfh, *pfl, *pmidh, *pmidl, *pwh, *pwl;
    cudaGetSymbolAddress((void**)&pv, g_v);
    cudaGetSymbolAddress((void**)&poff, g_off);
    cudaGetSymbolAddress((void**)&pattn, g_attn);
    cudaGetSymbolAddress((void**)&pqh, g_qh);
    cudaGetSymbolAddress((void**)&pql, g_ql);
    cudaGetSymbolAddress((void**)&pfh, g_fh);
    cudaGetSymbolAddress((void**)&pfl, g_fl);
    cudaGetSymbolAddress((void**)&pmidh, g_midh);
    cudaGetSymbolAddress((void**)&pmidl, g_midl);
    cudaGetSymbolAddress((void**)&pwh, g_wh);
    cudaGetSymbolAddress((void**)&pwl, g_wl);

    static bool attrSet = false;
    if (!attrSet) {
        cudaFuncSetAttribute(bf16_gemm, cudaFuncAttributeMaxDynamicSharedMemorySize, GEMM_SMEM);
        attrSet = true;
    }

    const int hw[3]  = {7680, 1920, 480};
    const int off[3] = {0, 7680, 9600};
    const float* feats[3] = {feat0, feat1, feat2};

    // ---- prep: q = x + pe, split ----
    {
        int n4 = B_ * NQ_ * DM_ / 4;
        add_split_kernel<<<(n4 + 255) / 256, 256>>>(x, pe, pqh, pql, n4);
    }
    // ---- prep: feature transpose+split ([256, hw] -> [hw, 256]) ----
    for (int l = 0; l < 3; l++) {
        dim3 grid((hw[l] + 31) / 32, DM_ / 32, B_);
        transpose_split_kernel<<<grid, 256>>>(feats[l],
            pfh + (long)off[l] * DM_, pfl + (long)off[l] * DM_,
            DM_, hw[l], (long)DM_ * hw[l], (long)TOTHW_ * DM_);
    }
    // ---- prep: weight transpose+split ([K,N] -> [N,K]) ----
    {
        dim3 g1((NHD_ + 31) / 32, DM_ / 32, 1);
        transpose_split_kernel<<<g1, 256>>>(W_value, pwh + WV_OFF, pwl + WV_OFF, DM_, NHD_, 0, 0);
        dim3 g2((NOFF_ + 31) / 32, DM_ / 32, 1);
        transpose_split_kernel<<<g2, 256>>>(W_off, pwh + WOFF_OFF, pwl + WOFF_OFF, DM_, NOFF_, 0, 0);
        dim3 g3((NATT_ + 31) / 32, DM_ / 32, 1);
        transpose_split_kernel<<<g3, 256>>>(W_attn, pwh + WATT_OFF, pwl + WATT_OFF, DM_, NATT_, 0, 0);
        dim3 g4((DM_ + 31) / 32, NHD_ / 32, 1);
        transpose_split_kernel<<<g4, 256>>>(W_out, pwh + WOUT_OFF, pwl + WOUT_OFF, NHD_, DM_, 0, 0);
    }

    // ---- GEMM 1: value projection (single fused launch, M = B*TOTHW) ----
    {
        dim3 grid(NHD_ / BN, (B_ * TOTHW_ + BM - 1) / BM);
        bf16_gemm<<<grid, 256, GEMM_SMEM>>>(pfh, pfl, pwh + WV_OFF, pwl + WV_OFF,
                                            b_value, pv, B_ * TOTHW_, NHD_, DM_);
    }
    // ---- GEMM 2: offsets ----
    {
        dim3 grid((NOFF_ + BN - 1) / BN, (B_ * NQ_) / BM);
        bf16_gemm<<<grid, 256, GEMM_SMEM>>>(pqh, pql, pwh + WOFF_OFF, pwl + WOFF_OFF,
                                            b_off, poff, B_ * NQ_, NOFF_, DM_);
    }
    // ---- GEMM 3: attention logits ----
    {
        dim3 grid((NATT_ + BN - 1) / BN, (B_ * NQ_) / BM);
        bf16_gemm<<<grid, 256, GEMM_SMEM>>>(pqh, pql, pwh + WATT_OFF, pwl + WATT_OFF,
                                            b_attn, pattn, B_ * NQ_, NATT_, DM_);
    }
    // ---- sampler ----
    {
        dim3 grid(NQ_, B_);
        sample_kernel<<<grid, 384>>>(coor, cam2img, lidar2cam);
    }
    // ---- GEMM 4: output projection ----
    {
        dim3 grid(DM_ / BN, (B_ * NQ_) / BM);
        bf16_gemm<<<grid, 256, GEMM_SMEM>>>(pmidh, pmidl, pwh + WOUT_OFF, pwl + WOUT_OFF,
                                            b_out, out, B_ * NQ_, DM_, NHD_);
    }
}